// round 5
// baseline (speedup 1.0000x reference)
#include <cuda_runtime.h>

// LSTM: B=4096, T=512, I=1, H=64, O=1. PyTorch gate order (i,f,g,o).
// Round 4 = round-2 kernel resubmitted verbatim (round-3 bench was an infra
// failure; need the measurement before changing anything).
//   block = 256 thr = 8 warps, 16 batches (lane&15 = batch).
//   half = lane>>4 selects j-block: warp w covers j in [4w,4w+4) (half 0)
//   and [32+4w, 32+4w+4) (half 1). W interleaved so both halves' 16B records
//   sit in one 32B span -> one LDS.128 per (j-pair-slot, k), 1 wavefront.
//   h stored duplicated pack2(h,h), loaded as k-pairs (LDS.128).
//   grid = 256 blocks, 2 CTAs/SM.

#define T_LEN 512
#define HID   64
#define BTILE 16
#define NTHREADS 256
#define JPL   4            // j per lane
#define HSTRIDE 66         // u64 stride per batch row: 528B = 16-aligned

typedef unsigned long long ull;

__device__ __forceinline__ void fma2(ull& acc, ull a, ull b) {
    asm("fma.rn.f32x2 %0, %1, %2, %0;" : "+l"(acc) : "l"(a), "l"(b));
}
__device__ __forceinline__ ull pack2(float lo, float hi) {
    ull r; asm("mov.b64 %0, {%1, %2};" : "=l"(r) : "f"(lo), "f"(hi)); return r;
}
__device__ __forceinline__ void unpack2(ull v, float& lo, float& hi) {
    asm("mov.b64 {%0, %1}, %2;" : "=f"(lo), "=f"(hi) : "l"(v));
}
__device__ __forceinline__ float ex2_fast(float x) {
    float y; asm("ex2.approx.f32 %0, %1;" : "=f"(y) : "f"(x)); return y;
}
__device__ __forceinline__ float rcp_fast(float x) {
    float y; asm("rcp.approx.f32 %0, %1;" : "=f"(y) : "f"(x)); return y;
}
// sigmoid(x) = 1 / (1 + 2^(-x*log2e));  accurate to ~1e-6, no NaN paths
__device__ __forceinline__ float sigmoid_fast(float x) {
    float e = ex2_fast(-1.4426950408889634f * x);
    return rcp_fast(1.0f + e);
}
// tanh(x) = 2*sigmoid(2x) - 1  (safe at both infinities)
__device__ __forceinline__ float tanh_fast(float x) {
    float e = ex2_fast(-2.8853900817779268f * x);
    return fmaf(2.0f, rcp_fast(1.0f + e), -1.0f);
}

// Shared layout (bytes):
//   WshI : ulonglong2[32*64*2] = 65536
//          entry ((j2*64 + k)*2 + half) = { pack(Wi,Wf), pack(Wg,Wo) } for j = j2 + 32*half
//   Hsh  : ull[16*66]          = 8448   (Hsh[b*66+k] = pack(h,h))
//   bsh  : float4[64]          = 1024
//   wxsh : float4[64]          = 1024
#define SMEM_W_OFF   0
#define SMEM_H_OFF   65536
#define SMEM_B_OFF   (65536 + 8448)
#define SMEM_WX_OFF  (65536 + 8448 + 1024)
#define SMEM_BYTES   (65536 + 8448 + 1024 + 1024)

__global__ void __launch_bounds__(NTHREADS, 2)
lstm_kernel(const float* __restrict__ x,
            const float* __restrict__ w_ih,
            const float* __restrict__ w_hh,
            const float* __restrict__ b_ih,
            const float* __restrict__ b_hh,
            const float* __restrict__ w_out,
            const float* __restrict__ b_out,
            float* __restrict__ out)
{
    extern __shared__ __align__(16) unsigned char smem[];
    ulonglong2* WshI = (ulonglong2*)(smem + SMEM_W_OFF);
    ull*        Hsh  = (ull*)       (smem + SMEM_H_OFF);
    float4*     bsh  = (float4*)    (smem + SMEM_B_OFF);
    float4*     wxsh = (float4*)    (smem + SMEM_WX_OFF);

    const int tid   = threadIdx.x;
    const int lane  = tid & 31;
    const int warp  = tid >> 5;
    const int half  = lane >> 4;           // 0: j in [4w,4w+4), 1: j in [32+4w, ...)
    const int bloc  = lane & 15;           // local batch
    const int j2b   = warp * JPL;          // base j2 for this warp (0..28)
    const int jlane = j2b + 32 * half;     // actual first j for this lane
    const int b     = blockIdx.x * BTILE + bloc;

    // ---- one-time prep ----
    for (int e = tid; e < 32 * 64 * 2; e += NTHREADS) {
        int hf = e & 1;
        int k  = (e >> 1) & 63;
        int j2 = e >> 7;
        int j  = j2 + 32 * hf;
        float wi = w_hh[(0 * HID + j) * HID + k];
        float wf = w_hh[(1 * HID + j) * HID + k];
        float wg = w_hh[(2 * HID + j) * HID + k];
        float wo = w_hh[(3 * HID + j) * HID + k];
        ulonglong2 v; v.x = pack2(wi, wf); v.y = pack2(wg, wo);
        WshI[e] = v;
    }
    for (int s = tid; s < HID; s += NTHREADS) {
        float4 bv, wv;
        bv.x = b_ih[0 * HID + s] + b_hh[0 * HID + s];
        bv.y = b_ih[1 * HID + s] + b_hh[1 * HID + s];
        bv.z = b_ih[2 * HID + s] + b_hh[2 * HID + s];
        bv.w = b_ih[3 * HID + s] + b_hh[3 * HID + s];
        wv.x = w_ih[0 * HID + s];
        wv.y = w_ih[1 * HID + s];
        wv.z = w_ih[2 * HID + s];
        wv.w = w_ih[3 * HID + s];
        bsh[s] = bv; wxsh[s] = wv;
    }
    for (int s = tid; s < BTILE * HSTRIDE; s += NTHREADS) Hsh[s] = 0ull;
    __syncthreads();

    float c[JPL];
#pragma unroll
    for (int j = 0; j < JPL; ++j) c[j] = 0.0f;

    const float4* x4 = (const float4*)x + ((b * T_LEN) >> 2);
    const ulonglong2* hrow2 = (const ulonglong2*)(Hsh + bloc * HSTRIDE);
    ulonglong2* hwr2 = (ulonglong2*)(Hsh + bloc * HSTRIDE + jlane);
    const ulonglong2* Wp = WshI + half;

    for (int t0 = 0; t0 < T_LEN; t0 += 4) {
        float4 xv = x4[t0 >> 2];
        float xts[4] = {xv.x, xv.y, xv.z, xv.w};
#pragma unroll
        for (int tt = 0; tt < 4; ++tt) {
            const float xt = xts[tt];
            ull aif[JPL], ago[JPL];
#pragma unroll
            for (int j = 0; j < JPL; ++j) {
                float4 bj = bsh[jlane + j];
                float4 wj = wxsh[jlane + j];
                aif[j] = pack2(fmaf(xt, wj.x, bj.x), fmaf(xt, wj.y, bj.y));
                ago[j] = pack2(fmaf(xt, wj.z, bj.z), fmaf(xt, wj.w, bj.w));
            }
            // gates += sum_k h[k] * W[j][k]  (k processed in pairs)
#pragma unroll 2
            for (int kp = 0; kp < HID / 2; ++kp) {
                ulonglong2 h2 = hrow2[kp];
#pragma unroll
                for (int j = 0; j < JPL; ++j) {
                    ulonglong2 w0 = Wp[((j2b + j) * 64 + 2 * kp) * 2];
                    ulonglong2 w1 = Wp[((j2b + j) * 64 + 2 * kp + 1) * 2];
                    fma2(aif[j], h2.x, w0.x);
                    fma2(ago[j], h2.x, w0.y);
                    fma2(aif[j], h2.y, w1.x);
                    fma2(ago[j], h2.y, w1.y);
                }
            }
            __syncthreads();   // all reads of h done before overwrite
            float hv[JPL];
#pragma unroll
            for (int j = 0; j < JPL; ++j) {
                float gi, gf, gg, go;
                unpack2(aif[j], gi, gf);
                unpack2(ago[j], gg, go);
                float ii = sigmoid_fast(gi);
                float ff = sigmoid_fast(gf);
                float g  = tanh_fast(gg);
                float oo = sigmoid_fast(go);
                c[j] = fmaf(ff, c[j], ii * g);
                hv[j] = oo * tanh_fast(c[j]);
            }
            {
                ulonglong2 s0, s1;
                s0.x = pack2(hv[0], hv[0]); s0.y = pack2(hv[1], hv[1]);
                s1.x = pack2(hv[2], hv[2]); s1.y = pack2(hv[3], hv[3]);
                hwr2[0] = s0; hwr2[1] = s1;
            }
            __syncthreads();   // h writes visible before next step
        }
    }

    // output: out[b] = h_T[b,:] @ w_out + b_out  (warp 0, lanes 0-15)
    if (warp == 0 && lane < 16) {
        float acc = b_out[0];
        const ull* hr = Hsh + bloc * HSTRIDE;
#pragma unroll 8
        for (int k = 0; k < HID; ++k) {
            float hk = __uint_as_float((unsigned)(hr[k] & 0xffffffffull));
            acc = fmaf(hk, w_out[k], acc);
        }
        out[b] = acc;
    }
}

extern "C" void kernel_launch(void* const* d_in, const int* in_sizes, int n_in,
                              void* d_out, int out_size) {
    const float* x     = (const float*)d_in[0];
    const float* w_ih  = (const float*)d_in[1];
    const float* w_hh  = (const float*)d_in[2];
    const float* b_ih  = (const float*)d_in[3];
    const float* b_hh  = (const float*)d_in[4];
    const float* w_out = (const float*)d_in[5];
    const float* b_out = (const float*)d_in[6];
    float* out = (float*)d_out;

    cudaFuncSetAttribute(lstm_kernel,
                         cudaFuncAttributeMaxDynamicSharedMemorySize, SMEM_BYTES);
    lstm_kernel<<<4096 / BTILE, NTHREADS, SMEM_BYTES>>>(
        x, w_ih, w_hh, b_ih, b_hh, w_out, b_out, out);
}

// round 6
// speedup vs baseline: 1.1082x; 1.1082x over previous
#include <cuda_runtime.h>

// LSTM: B=4096, T=512, I=1, H=64, O=1. PyTorch gate order (i,f,g,o).
// Round 5: round-1 structure (8 warps, lane=batch, 8 j per warp) +
//   (a) double-buffered h -> ONE barrier per timestep,
//   (b) h stored single f32, loaded as float2 pairs (2 wf), packed in regs,
//   (c) bias + x*w_ih deferred to epilogue (accs start at 0, fewer live regs),
//   (d) x prefetch, 2 CTAs/SM.

#define T_LEN 512
#define HID   64
#define BTILE 32
#define NTHREADS 256
#define JPL   8            // hidden units per warp (8 warps * 8 = 64)
#define HROW  66           // floats per batch row (even stride: aligned float2, 2 wf)

typedef unsigned long long ull;

__device__ __forceinline__ void fma2(ull& acc, ull a, ull b) {
    asm("fma.rn.f32x2 %0, %1, %2, %0;" : "+l"(acc) : "l"(a), "l"(b));
}
__device__ __forceinline__ ull pack2(float lo, float hi) {
    ull r; asm("mov.b64 %0, {%1, %2};" : "=l"(r) : "f"(lo), "f"(hi)); return r;
}
__device__ __forceinline__ void unpack2(ull v, float& lo, float& hi) {
    asm("mov.b64 {%0, %1}, %2;" : "=f"(lo), "=f"(hi) : "l"(v));
}
__device__ __forceinline__ float ex2_fast(float x) {
    float y; asm("ex2.approx.f32 %0, %1;" : "=f"(y) : "f"(x)); return y;
}
__device__ __forceinline__ float rcp_fast(float x) {
    float y; asm("rcp.approx.f32 %0, %1;" : "=f"(y) : "f"(x)); return y;
}
// sigmoid(x) = 1 / (1 + 2^(-x*log2e));  accurate ~1e-6, no NaN paths
__device__ __forceinline__ float sigmoid_fast(float x) {
    float e = ex2_fast(-1.4426950408889634f * x);
    return rcp_fast(1.0f + e);
}
// tanh(x) = 2*sigmoid(2x) - 1  (safe at both infinities)
__device__ __forceinline__ float tanh_fast(float x) {
    float e = ex2_fast(-2.8853900817779268f * x);
    return fmaf(2.0f, rcp_fast(1.0f + e), -1.0f);
}

// Shared layout (bytes):
//   Wsh : ulonglong2[64*64] = 65536   Wsh[j*64+k] = { pack(Wi,Wf), pack(Wg,Wo) }
//   Hsh : float[2][32*66]   = 16896   (double buffer, single-width h)
//   bsh : float4[64]        = 1024    combined bias per j (i,f,g,o)
//   wxsh: float4[64]        = 1024    w_ih per j (i,f,g,o)
#define SMEM_W_OFF   0
#define SMEM_H_OFF   65536
#define SMEM_B_OFF   (65536 + 16896)
#define SMEM_WX_OFF  (65536 + 16896 + 1024)
#define SMEM_BYTES   (65536 + 16896 + 1024 + 1024)

__global__ void __launch_bounds__(NTHREADS, 2)
lstm_kernel(const float* __restrict__ x,
            const float* __restrict__ w_ih,
            const float* __restrict__ w_hh,
            const float* __restrict__ b_ih,
            const float* __restrict__ b_hh,
            const float* __restrict__ w_out,
            const float* __restrict__ b_out,
            float* __restrict__ out)
{
    extern __shared__ __align__(16) unsigned char smem[];
    ulonglong2* Wsh  = (ulonglong2*)(smem + SMEM_W_OFF);
    float*      Hsh0 = (float*)     (smem + SMEM_H_OFF);
    float*      Hsh1 = Hsh0 + BTILE * HROW;
    float4*     bsh  = (float4*)    (smem + SMEM_B_OFF);
    float4*     wxsh = (float4*)    (smem + SMEM_WX_OFF);

    const int tid  = threadIdx.x;
    const int lane = tid & 31;
    const int warp = tid >> 5;
    const int jb   = warp * JPL;
    const int b    = blockIdx.x * BTILE + lane;

    // ---- one-time prep: gate-interleave w_hh into shared ----
    for (int s = tid; s < HID * HID; s += NTHREADS) {
        int j = s >> 6, k = s & 63;
        float wi = w_hh[(0 * HID + j) * HID + k];
        float wf = w_hh[(1 * HID + j) * HID + k];
        float wg = w_hh[(2 * HID + j) * HID + k];
        float wo = w_hh[(3 * HID + j) * HID + k];
        ulonglong2 v; v.x = pack2(wi, wf); v.y = pack2(wg, wo);
        Wsh[s] = v;
    }
    for (int s = tid; s < HID; s += NTHREADS) {
        float4 bv, wv;
        bv.x = b_ih[0 * HID + s] + b_hh[0 * HID + s];
        bv.y = b_ih[1 * HID + s] + b_hh[1 * HID + s];
        bv.z = b_ih[2 * HID + s] + b_hh[2 * HID + s];
        bv.w = b_ih[3 * HID + s] + b_hh[3 * HID + s];
        wv.x = w_ih[0 * HID + s];
        wv.y = w_ih[1 * HID + s];
        wv.z = w_ih[2 * HID + s];
        wv.w = w_ih[3 * HID + s];
        bsh[s] = bv; wxsh[s] = wv;
    }
    // zero buffer 0 only (buffer 1 is written at t=0 before first read at t=1)
    for (int s = tid; s < BTILE * HROW; s += NTHREADS) Hsh0[s] = 0.0f;
    __syncthreads();

    float c[JPL];
#pragma unroll
    for (int j = 0; j < JPL; ++j) c[j] = 0.0f;

    const float4* x4 = (const float4*)x + b * (T_LEN / 4);
    const ulonglong2* Wrow = Wsh + jb * HID;

    float4 xv = x4[0];

    for (int t0 = 0; t0 < T_LEN; t0 += 4) {
        // prefetch next group's x (clamped; last iteration re-reads valid data)
        int nidx = t0 / 4 + 1;
        if (nidx > T_LEN / 4 - 1) nidx = T_LEN / 4 - 1;
        float4 xvn = x4[nidx];

        float xts[4] = {xv.x, xv.y, xv.z, xv.w};
#pragma unroll
        for (int tt = 0; tt < 4; ++tt) {
            const float xt = xts[tt];
            // t parity == tt parity (t0 is a multiple of 4)
            const float* hrd = (tt & 1) ? Hsh1 : Hsh0;
            float*       hwrb = (tt & 1) ? Hsh0 : Hsh1;
            const float2* hp = (const float2*)(hrd + lane * HROW);

            ull aif[JPL], ago[JPL];
#pragma unroll
            for (int j = 0; j < JPL; ++j) { aif[j] = 0ull; ago[j] = 0ull; }

            // gates[j] += sum_k h[k] * W[j][k]   (k in pairs; W broadcast)
#pragma unroll 4
            for (int kp = 0; kp < HID / 2; ++kp) {
                float2 h01 = hp[kp];
                ull h2a = pack2(h01.x, h01.x);
                ull h2b = pack2(h01.y, h01.y);
#pragma unroll
                for (int j = 0; j < JPL; ++j) {
                    ulonglong2 w0 = Wrow[j * HID + 2 * kp];
                    ulonglong2 w1 = Wrow[j * HID + 2 * kp + 1];
                    fma2(aif[j], h2a, w0.x);
                    fma2(ago[j], h2a, w0.y);
                    fma2(aif[j], h2b, w1.x);
                    fma2(ago[j], h2b, w1.y);
                }
            }

            // epilogue: add bias + x*w_ih, activations, state update
            float hv[JPL];
#pragma unroll
            for (int j = 0; j < JPL; ++j) {
                float gi, gf, gg, go;
                unpack2(aif[j], gi, gf);
                unpack2(ago[j], gg, go);
                float4 bj = bsh[jb + j];
                float4 wj = wxsh[jb + j];
                gi = fmaf(xt, wj.x, gi + bj.x);
                gf = fmaf(xt, wj.y, gf + bj.y);
                gg = fmaf(xt, wj.z, gg + bj.z);
                go = fmaf(xt, wj.w, go + bj.w);
                float ii = sigmoid_fast(gi);
                float ff = sigmoid_fast(gf);
                float g  = tanh_fast(gg);
                float oo = sigmoid_fast(go);
                c[j] = fmaf(ff, c[j], ii * g);
                hv[j] = oo * tanh_fast(c[j]);
            }
            {
                float2* hw = (float2*)(hwrb + lane * HROW + jb);
                hw[0] = make_float2(hv[0], hv[1]);
                hw[1] = make_float2(hv[2], hv[3]);
                hw[2] = make_float2(hv[4], hv[5]);
                hw[3] = make_float2(hv[6], hv[7]);
            }
            __syncthreads();   // single barrier per step (double-buffered h)
        }
        xv = xvn;
    }

    // last step t=511 wrote buffer 0
    if (warp == 0) {
        float acc = b_out[0];
        const float* hr = Hsh0 + lane * HROW;
#pragma unroll 8
        for (int k = 0; k < HID; ++k)
            acc = fmaf(hr[k], w_out[k], acc);
        out[b] = acc;
    }
}

extern "C" void kernel_launch(void* const* d_in, const int* in_sizes, int n_in,
                              void* d_out, int out_size) {
    const float* x     = (const float*)d_in[0];
    const float* w_ih  = (const float*)d_in[1];
    const float* w_hh  = (const float*)d_in[2];
    const float* b_ih  = (const float*)d_in[3];
    const float* b_hh  = (const float*)d_in[4];
    const float* w_out = (const float*)d_in[5];
    const float* b_out = (const float*)d_in[6];
    float* out = (float*)d_out;

    cudaFuncSetAttribute(lstm_kernel,
                         cudaFuncAttributeMaxDynamicSharedMemorySize, SMEM_BYTES);
    lstm_kernel<<<4096 / BTILE, NTHREADS, SMEM_BYTES>>>(
        x, w_ih, w_hh, b_ih, b_hh, w_out, b_out, out);
}

// round 7
// speedup vs baseline: 1.1114x; 1.0029x over previous
#include <cuda_runtime.h>

// LSTM: B=4096, T=512, I=1, H=64, O=1. PyTorch gate order (i,f,g,o).
// Round 5: round-1 structure (8 warps, lane=batch, 8 j per warp) +
//   (a) double-buffered h -> ONE barrier per timestep,
//   (b) h stored single f32, loaded as float2 pairs (2 wf), packed in regs,
//   (c) bias + x*w_ih deferred to epilogue (accs start at 0, fewer live regs),
//   (d) x prefetch, 2 CTAs/SM.

#define T_LEN 512
#define HID   64
#define BTILE 32
#define NTHREADS 256
#define JPL   8            // hidden units per warp (8 warps * 8 = 64)
#define HROW  66           // floats per batch row (even stride: aligned float2, 2 wf)

typedef unsigned long long ull;

__device__ __forceinline__ void fma2(ull& acc, ull a, ull b) {
    asm("fma.rn.f32x2 %0, %1, %2, %0;" : "+l"(acc) : "l"(a), "l"(b));
}
__device__ __forceinline__ ull pack2(float lo, float hi) {
    ull r; asm("mov.b64 %0, {%1, %2};" : "=l"(r) : "f"(lo), "f"(hi)); return r;
}
__device__ __forceinline__ void unpack2(ull v, float& lo, float& hi) {
    asm("mov.b64 {%0, %1}, %2;" : "=f"(lo), "=f"(hi) : "l"(v));
}
__device__ __forceinline__ float ex2_fast(float x) {
    float y; asm("ex2.approx.f32 %0, %1;" : "=f"(y) : "f"(x)); return y;
}
__device__ __forceinline__ float rcp_fast(float x) {
    float y; asm("rcp.approx.f32 %0, %1;" : "=f"(y) : "f"(x)); return y;
}
// sigmoid(x) = 1 / (1 + 2^(-x*log2e));  accurate ~1e-6, no NaN paths
__device__ __forceinline__ float sigmoid_fast(float x) {
    float e = ex2_fast(-1.4426950408889634f * x);
    return rcp_fast(1.0f + e);
}
// tanh(x) = 2*sigmoid(2x) - 1  (safe at both infinities)
__device__ __forceinline__ float tanh_fast(float x) {
    float e = ex2_fast(-2.8853900817779268f * x);
    return fmaf(2.0f, rcp_fast(1.0f + e), -1.0f);
}

// Shared layout (bytes):
//   Wsh : ulonglong2[64*64] = 65536   Wsh[j*64+k] = { pack(Wi,Wf), pack(Wg,Wo) }
//   Hsh : float[2][32*66]   = 16896   (double buffer, single-width h)
//   bsh : float4[64]        = 1024    combined bias per j (i,f,g,o)
//   wxsh: float4[64]        = 1024    w_ih per j (i,f,g,o)
#define SMEM_W_OFF   0
#define SMEM_H_OFF   65536
#define SMEM_B_OFF   (65536 + 16896)
#define SMEM_WX_OFF  (65536 + 16896 + 1024)
#define SMEM_BYTES   (65536 + 16896 + 1024 + 1024)

__global__ void __launch_bounds__(NTHREADS, 2)
lstm_kernel(const float* __restrict__ x,
            const float* __restrict__ w_ih,
            const float* __restrict__ w_hh,
            const float* __restrict__ b_ih,
            const float* __restrict__ b_hh,
            const float* __restrict__ w_out,
            const float* __restrict__ b_out,
            float* __restrict__ out)
{
    extern __shared__ __align__(16) unsigned char smem[];
    ulonglong2* Wsh  = (ulonglong2*)(smem + SMEM_W_OFF);
    float*      Hsh0 = (float*)     (smem + SMEM_H_OFF);
    float*      Hsh1 = Hsh0 + BTILE * HROW;
    float4*     bsh  = (float4*)    (smem + SMEM_B_OFF);
    float4*     wxsh = (float4*)    (smem + SMEM_WX_OFF);

    const int tid  = threadIdx.x;
    const int lane = tid & 31;
    const int warp = tid >> 5;
    const int jb   = warp * JPL;
    const int b    = blockIdx.x * BTILE + lane;

    // ---- one-time prep: gate-interleave w_hh into shared ----
    for (int s = tid; s < HID * HID; s += NTHREADS) {
        int j = s >> 6, k = s & 63;
        float wi = w_hh[(0 * HID + j) * HID + k];
        float wf = w_hh[(1 * HID + j) * HID + k];
        float wg = w_hh[(2 * HID + j) * HID + k];
        float wo = w_hh[(3 * HID + j) * HID + k];
        ulonglong2 v; v.x = pack2(wi, wf); v.y = pack2(wg, wo);
        Wsh[s] = v;
    }
    for (int s = tid; s < HID; s += NTHREADS) {
        float4 bv, wv;
        bv.x = b_ih[0 * HID + s] + b_hh[0 * HID + s];
        bv.y = b_ih[1 * HID + s] + b_hh[1 * HID + s];
        bv.z = b_ih[2 * HID + s] + b_hh[2 * HID + s];
        bv.w = b_ih[3 * HID + s] + b_hh[3 * HID + s];
        wv.x = w_ih[0 * HID + s];
        wv.y = w_ih[1 * HID + s];
        wv.z = w_ih[2 * HID + s];
        wv.w = w_ih[3 * HID + s];
        bsh[s] = bv; wxsh[s] = wv;
    }
    // zero buffer 0 only (buffer 1 is written at t=0 before first read at t=1)
    for (int s = tid; s < BTILE * HROW; s += NTHREADS) Hsh0[s] = 0.0f;
    __syncthreads();

    float c[JPL];
#pragma unroll
    for (int j = 0; j < JPL; ++j) c[j] = 0.0f;

    const float4* x4 = (const float4*)x + b * (T_LEN / 4);
    const ulonglong2* Wrow = Wsh + jb * HID;

    float4 xv = x4[0];

    for (int t0 = 0; t0 < T_LEN; t0 += 4) {
        // prefetch next group's x (clamped; last iteration re-reads valid data)
        int nidx = t0 / 4 + 1;
        if (nidx > T_LEN / 4 - 1) nidx = T_LEN / 4 - 1;
        float4 xvn = x4[nidx];

        float xts[4] = {xv.x, xv.y, xv.z, xv.w};
#pragma unroll
        for (int tt = 0; tt < 4; ++tt) {
            const float xt = xts[tt];
            // t parity == tt parity (t0 is a multiple of 4)
            const float* hrd = (tt & 1) ? Hsh1 : Hsh0;
            float*       hwrb = (tt & 1) ? Hsh0 : Hsh1;
            const float2* hp = (const float2*)(hrd + lane * HROW);

            ull aif[JPL], ago[JPL];
#pragma unroll
            for (int j = 0; j < JPL; ++j) { aif[j] = 0ull; ago[j] = 0ull; }

            // gates[j] += sum_k h[k] * W[j][k]   (k in pairs; W broadcast)
#pragma unroll 4
            for (int kp = 0; kp < HID / 2; ++kp) {
                float2 h01 = hp[kp];
                ull h2a = pack2(h01.x, h01.x);
                ull h2b = pack2(h01.y, h01.y);
#pragma unroll
                for (int j = 0; j < JPL; ++j) {
                    ulonglong2 w0 = Wrow[j * HID + 2 * kp];
                    ulonglong2 w1 = Wrow[j * HID + 2 * kp + 1];
                    fma2(aif[j], h2a, w0.x);
                    fma2(ago[j], h2a, w0.y);
                    fma2(aif[j], h2b, w1.x);
                    fma2(ago[j], h2b, w1.y);
                }
            }

            // epilogue: add bias + x*w_ih, activations, state update
            float hv[JPL];
#pragma unroll
            for (int j = 0; j < JPL; ++j) {
                float gi, gf, gg, go;
                unpack2(aif[j], gi, gf);
                unpack2(ago[j], gg, go);
                float4 bj = bsh[jb + j];
                float4 wj = wxsh[jb + j];
                gi = fmaf(xt, wj.x, gi + bj.x);
                gf = fmaf(xt, wj.y, gf + bj.y);
                gg = fmaf(xt, wj.z, gg + bj.z);
                go = fmaf(xt, wj.w, go + bj.w);
                float ii = sigmoid_fast(gi);
                float ff = sigmoid_fast(gf);
                float g  = tanh_fast(gg);
                float oo = sigmoid_fast(go);
                c[j] = fmaf(ff, c[j], ii * g);
                hv[j] = oo * tanh_fast(c[j]);
            }
            {
                float2* hw = (float2*)(hwrb + lane * HROW + jb);
                hw[0] = make_float2(hv[0], hv[1]);
                hw[1] = make_float2(hv[2], hv[3]);
                hw[2] = make_float2(hv[4], hv[5]);
                hw[3] = make_float2(hv[6], hv[7]);
            }
            __syncthreads();   // single barrier per step (double-buffered h)
        }
        xv = xvn;
    }

    // last step t=511 wrote buffer 0
    if (warp == 0) {
        float acc = b_out[0];
        const float* hr = Hsh0 + lane * HROW;
#pragma unroll 8
        for (int k = 0; k < HID; ++k)
            acc = fmaf(hr[k], w_out[k], acc);
        out[b] = acc;
    }
}

extern "C" void kernel_launch(void* const* d_in, const int* in_sizes, int n_in,
                              void* d_out, int out_size) {
    const float* x     = (const float*)d_in[0];
    const float* w_ih  = (const float*)d_in[1];
    const float* w_hh  = (const float*)d_in[2];
    const float* b_ih  = (const float*)d_in[3];
    const float* b_hh  = (const float*)d_in[4];
    const float* w_out = (const float*)d_in[5];
    const float* b_out = (const float*)d_in[6];
    float* out = (float*)d_out;

    cudaFuncSetAttribute(lstm_kernel,
                         cudaFuncAttributeMaxDynamicSharedMemorySize, SMEM_BYTES);
    lstm_kernel<<<4096 / BTILE, NTHREADS, SMEM_BYTES>>>(
        x, w_ih, w_hh, b_ih, b_hh, w_out, b_out, out);
}

// round 9
// speedup vs baseline: 3.5346x; 3.1802x over previous
#include <cuda_runtime.h>
#include <cuda_bf16.h>
#include <cstdint>

// LSTM B=4096 T=512 I=1 H=64 O=1, PyTorch gate order (i,f,g,o).
// mma.sync (HMMA) path — plain PTX ISA, works on sm_103 (no 'a' features).
//   CTA: 32 batches, 8 warps, grid 128.
//   gates[32,256] = h[32,64] @ w_hh^T as m16n8k16 bf16 MMAs, fp32 accum,
//   2-way bf16 split of both h and W: 3 terms (HH, HL, LH).
//   N layout gate-major: col n = g*64 + j. Warp w owns j in [8w,8w+8):
//   its 4 n8-tiles (one per gate) put all 4 gates of a (b,j) in ONE thread.
//   W B-fragments persist in registers (loaded once — no smem W traffic!).
//   h: bf16 hi/lo arrays in smem, 144B row stride (conflict-free STS.32 +
//   ldmatrix), double buffered -> 1 __syncthreads per step.

#define T_LEN 512
#define HID   64
#define NTHREADS 256
#define HS   144            // h row stride (bytes): 16B-aligned, bank-spreading
#define HSZ  (32 * HS)      // one h array: 4608 B
#define XS   516            // x row stride (floats): bank-spreading
#define OFF_H 0             // [buf][part] 4 arrays: b0hi, b0lo, b1hi, b1lo
#define OFF_X (4 * HSZ)     // 18432
#define SMEM_BYTES (OFF_X + 32 * XS * 4)   // 18432 + 66048 = 84480

static __device__ __forceinline__ uint32_t smem_u32(const void* p) {
    uint32_t a;
    asm("{ .reg .u64 t; cvta.to.shared.u64 t, %1; cvt.u32.u64 %0, t; }"
        : "=r"(a) : "l"(p));
    return a;
}
static __device__ __forceinline__ void mma16816(float* d, const uint32_t* a,
                                                const uint32_t* b) {
    asm volatile(
        "mma.sync.aligned.m16n8k16.row.col.f32.bf16.bf16.f32 "
        "{%0,%1,%2,%3}, {%4,%5,%6,%7}, {%8,%9}, {%0,%1,%2,%3};"
        : "+f"(d[0]), "+f"(d[1]), "+f"(d[2]), "+f"(d[3])
        : "r"(a[0]), "r"(a[1]), "r"(a[2]), "r"(a[3]), "r"(b[0]), "r"(b[1]));
}
static __device__ __forceinline__ void ldsm4(uint32_t* r, uint32_t addr) {
    asm volatile("ldmatrix.sync.aligned.m8n8.x4.shared.b16 {%0,%1,%2,%3}, [%4];"
                 : "=r"(r[0]), "=r"(r[1]), "=r"(r[2]), "=r"(r[3]) : "r"(addr));
}
static __device__ __forceinline__ float ex2f(float x) {
    float y; asm("ex2.approx.f32 %0, %1;" : "=f"(y) : "f"(x)); return y;
}
static __device__ __forceinline__ float rcpf(float x) {
    float y; asm("rcp.approx.f32 %0, %1;" : "=f"(y) : "f"(x)); return y;
}
static __device__ __forceinline__ float sigf(float x) {
    return rcpf(1.0f + ex2f(-1.4426950408889634f * x));
}
static __device__ __forceinline__ float tanhf_(float x) {
    return fmaf(2.0f, rcpf(1.0f + ex2f(-2.8853900817779268f * x)), -1.0f);
}
static __device__ __forceinline__ uint32_t packbf(float a, float b) {
    __nv_bfloat16 ha = __float2bfloat16_rn(a), hb = __float2bfloat16_rn(b);
    uint32_t r;
    asm("mov.b32 %0, {%1, %2};" : "=r"(r)
        : "h"(__bfloat16_as_ushort(ha)), "h"(__bfloat16_as_ushort(hb)));
    return r;
}

__global__ void __launch_bounds__(NTHREADS, 1)
lstm_hmma_kernel(const float* __restrict__ x,
                 const float* __restrict__ w_ih,
                 const float* __restrict__ w_hh,
                 const float* __restrict__ b_ih,
                 const float* __restrict__ b_hh,
                 const float* __restrict__ w_out,
                 const float* __restrict__ b_out,
                 float* __restrict__ out)
{
    extern __shared__ __align__(16) unsigned char smem[];
    const uint32_t sb = smem_u32(smem);
    float* Xsf = (float*)(smem + OFF_X);

    const int tid  = threadIdx.x;
    const int lane = tid & 31;
    const int warp = tid >> 5;
    const int gid  = lane >> 2;     // group id (0..7)
    const int tig  = lane & 3;      // thread in group
    const int B0   = blockIdx.x * 32;

    // ---- W B-fragments in registers (persist across all 512 steps) ----
    // tile (g, kc): W row n = g*64 + 8*warp + gid; k = 16kc + {2tig,+1,+8,+9}
    uint32_t Whi[4][4][2], Wlo[4][4][2];
#pragma unroll
    for (int g = 0; g < 4; ++g)
#pragma unroll
        for (int kc = 0; kc < 4; ++kc) {
            int n = g * 64 + 8 * warp + gid;
            const float* wr = w_hh + n * HID + 16 * kc;
            float2 fa = *(const float2*)(wr + 2 * tig);
            float2 fb = *(const float2*)(wr + 2 * tig + 8);
            __nv_bfloat16 hax = __float2bfloat16_rn(fa.x);
            __nv_bfloat16 hay = __float2bfloat16_rn(fa.y);
            __nv_bfloat16 hbx = __float2bfloat16_rn(fb.x);
            __nv_bfloat16 hby = __float2bfloat16_rn(fb.y);
            Whi[g][kc][0] = packbf(fa.x, fa.y);
            Whi[g][kc][1] = packbf(fb.x, fb.y);
            Wlo[g][kc][0] = packbf(fa.x - __bfloat162float(hax),
                                   fa.y - __bfloat162float(hay));
            Wlo[g][kc][1] = packbf(fb.x - __bfloat162float(hbx),
                                   fb.y - __bfloat162float(hby));
        }

    // per-thread x-projection weights + combined bias: j = 8w + 2tig + jj
    float wihr[4][2], biasr[4][2];
#pragma unroll
    for (int g = 0; g < 4; ++g)
#pragma unroll
        for (int jj = 0; jj < 2; ++jj) {
            int n = g * 64 + 8 * warp + 2 * tig + jj;
            wihr[g][jj]  = w_ih[n];
            biasr[g][jj] = b_ih[n] + b_hh[n];
        }

    // ---- stage x[32, 512] into padded smem; zero h buffers ----
    for (int i = tid; i < 32 * (T_LEN / 4); i += NTHREADS) {
        int b = i / (T_LEN / 4), t4 = i % (T_LEN / 4);
        float4 v = ((const float4*)x)[(size_t)(B0 + b) * (T_LEN / 4) + t4];
        *(float4*)(Xsf + b * XS + 4 * t4) = v;
    }
    for (int i = tid; i < 4 * HSZ / 4; i += NTHREADS)
        ((uint32_t*)(smem + OFF_H))[i] = 0u;
    __syncthreads();

    // ldmatrix per-lane offset within an (mg, kc) tile group
    const uint32_t aoff =
        ((lane & 7) + 8 * ((lane >> 3) & 1)) * HS + 16 * ((lane >> 4) & 1);

    float c[8];
#pragma unroll
    for (int s = 0; s < 8; ++s) c[s] = 0.0f;

#pragma unroll 1
    for (int t = 0; t < T_LEN; ++t) {
        const int rb = t & 1;
        const uint32_t Hr = sb + OFF_H + (rb * 2) * HSZ;       // read hi
        unsigned char* Hwp = smem + OFF_H + ((rb ^ 1) * 2) * HSZ;  // write hi

        uint32_t A[2][4][4];
        float D[2][4][4];
#pragma unroll
        for (int mg = 0; mg < 2; ++mg)
#pragma unroll
            for (int g = 0; g < 4; ++g)
#pragma unroll
                for (int e = 0; e < 4; ++e) D[mg][g][e] = 0.0f;

        // A = h_hi; terms HH (W_hi) and HL (W_lo)
#pragma unroll
        for (int mg = 0; mg < 2; ++mg)
#pragma unroll
            for (int kc = 0; kc < 4; ++kc)
                ldsm4(A[mg][kc], Hr + mg * 16 * HS + kc * 32 + aoff);
#pragma unroll
        for (int mg = 0; mg < 2; ++mg)
#pragma unroll
            for (int kc = 0; kc < 4; ++kc)
#pragma unroll
                for (int g = 0; g < 4; ++g)
                    mma16816(D[mg][g], A[mg][kc], Whi[g][kc]);
#pragma unroll
        for (int mg = 0; mg < 2; ++mg)
#pragma unroll
            for (int kc = 0; kc < 4; ++kc)
#pragma unroll
                for (int g = 0; g < 4; ++g)
                    mma16816(D[mg][g], A[mg][kc], Wlo[g][kc]);
        // A = h_lo; term LH (W_hi)
#pragma unroll
        for (int mg = 0; mg < 2; ++mg)
#pragma unroll
            for (int kc = 0; kc < 4; ++kc)
                ldsm4(A[mg][kc], Hr + HSZ + mg * 16 * HS + kc * 32 + aoff);
#pragma unroll
        for (int mg = 0; mg < 2; ++mg)
#pragma unroll
            for (int kc = 0; kc < 4; ++kc)
#pragma unroll
                for (int g = 0; g < 4; ++g)
                    mma16816(D[mg][g], A[mg][kc], Whi[g][kc]);

        // epilogue: rows p = mg*2+rh -> batch row 8p+gid; j = 8w+2tig+jj
        float xv[4];
#pragma unroll
        for (int p = 0; p < 4; ++p) xv[p] = Xsf[(8 * p + gid) * XS + t];

#pragma unroll
        for (int mg = 0; mg < 2; ++mg)
#pragma unroll
            for (int rh = 0; rh < 2; ++rh) {
                float h2[2];
#pragma unroll
                for (int jj = 0; jj < 2; ++jj) {
                    const int di = rh * 2 + jj;
                    const int s  = mg * 4 + rh * 2 + jj;
                    const float xp = xv[mg * 2 + rh];
                    float Pi = D[mg][0][di] + fmaf(xp, wihr[0][jj], biasr[0][jj]);
                    float Pf = D[mg][1][di] + fmaf(xp, wihr[1][jj], biasr[1][jj]);
                    float Pg = D[mg][2][di] + fmaf(xp, wihr[2][jj], biasr[2][jj]);
                    float Po = D[mg][3][di] + fmaf(xp, wihr[3][jj], biasr[3][jj]);
                    float ii = sigf(Pi);
                    float ff = sigf(Pf);
                    float gg = tanhf_(Pg);
                    float oo = sigf(Po);
                    float cs = fmaf(ff, c[s], ii * gg);
                    c[s] = cs;
                    h2[jj] = oo * tanhf_(cs);
                }
                __nv_bfloat16 h0 = __float2bfloat16_rn(h2[0]);
                __nv_bfloat16 h1 = __float2bfloat16_rn(h2[1]);
                uint32_t phi = packbf(h2[0], h2[1]);
                uint32_t plo = packbf(h2[0] - __bfloat162float(h0),
                                      h2[1] - __bfloat162float(h1));
                unsigned char* wp = Hwp + (16 * mg + 8 * rh + gid) * HS
                                        + 16 * warp + 4 * tig;
                *(uint32_t*)wp = phi;
                *(uint32_t*)(wp + HSZ) = plo;
            }
        __syncthreads();
    }

    // final h is in buffer 0 (t=511 wrote rb^1 = 0)
    if (tid < 32) {
        const int b = tid;
        float acc = b_out[0];
        const unsigned char* hr = smem + OFF_H + b * HS;
#pragma unroll 8
        for (int k = 0; k < HID; ++k) {
            float hi = __bfloat162float(*(const __nv_bfloat16*)(hr + 2 * k));
            float lo = __bfloat162float(*(const __nv_bfloat16*)(hr + HSZ + 2 * k));
            acc = fmaf(hi + lo, w_out[k], acc);
        }
        out[B0 + b] = acc;
    }
}

extern "C" void kernel_launch(void* const* d_in, const int* in_sizes, int n_in,
                              void* d_out, int out_size) {
    const float* x     = (const float*)d_in[0];
    const float* w_ih  = (const float*)d_in[1];
    const float* w_hh  = (const float*)d_in[2];
    const float* b_ih  = (const float*)d_in[3];
    const float* b_hh  = (const float*)d_in[4];
    const float* w_out = (const float*)d_in[5];
    const float* b_out = (const float*)d_in[6];
    float* out = (float*)d_out;

    cudaFuncSetAttribute(lstm_hmma_kernel,
                         cudaFuncAttributeMaxDynamicSharedMemorySize, SMEM_BYTES);
    lstm_hmma_kernel<<<4096 / 32, NTHREADS, SMEM_BYTES>>>(
        x, w_ih, w_hh, b_ih, b_hh, w_out, b_out, out);
}

// round 15
// speedup vs baseline: 3.7284x; 1.0548x over previous
#include <cuda_runtime.h>
#include <cuda_bf16.h>
#include <cstdint>

// LSTM B=4096 T=512 I=1 H=64 O=1, PyTorch gate order (i,f,g,o).
// Round 10 = round-9 kernel resubmitted verbatim (round-9 bench died at
// device acquisition — infra, not kernel; measurement still needed).
//   HMMA path, 16 warps (512 thr) per CTA of 32 batches.
//   Warp pair (w, w+8): same j-block [8*(w&7), +8), rows 0-15 vs 16-31.
//   gates[32,256] = h[32,64] @ w_hh^T, m16n8k16 bf16, fp32 accum,
//   2-way bf16 split, 3 terms (HH, HL, LH). W frags persist in regs.
//   h bf16 hi/lo in smem (144B stride), double buffered, 1 bar/step.

#define T_LEN 512
#define HID   64
#define NTHREADS 512
#define HS   144
#define HSZ  (32 * HS)          // 4608
#define XS   516
#define OFF_H 0                 // 4 arrays: b0hi, b0lo, b1hi, b1lo
#define OFF_X (4 * HSZ)         // 18432
#define SMEM_BYTES (OFF_X + 32 * XS * 4)   // 84480

static __device__ __forceinline__ uint32_t smem_u32(const void* p) {
    uint32_t a;
    asm("{ .reg .u64 t; cvta.to.shared.u64 t, %1; cvt.u32.u64 %0, t; }"
        : "=r"(a) : "l"(p));
    return a;
}
static __device__ __forceinline__ void mma16816(float* d, const uint32_t* a,
                                                const uint32_t* b) {
    asm volatile(
        "mma.sync.aligned.m16n8k16.row.col.f32.bf16.bf16.f32 "
        "{%0,%1,%2,%3}, {%4,%5,%6,%7}, {%8,%9}, {%0,%1,%2,%3};"
        : "+f"(d[0]), "+f"(d[1]), "+f"(d[2]), "+f"(d[3])
        : "r"(a[0]), "r"(a[1]), "r"(a[2]), "r"(a[3]), "r"(b[0]), "r"(b[1]));
}
static __device__ __forceinline__ void ldsm4(uint32_t* r, uint32_t addr) {
    asm volatile("ldmatrix.sync.aligned.m8n8.x4.shared.b16 {%0,%1,%2,%3}, [%4];"
                 : "=r"(r[0]), "=r"(r[1]), "=r"(r[2]), "=r"(r[3]) : "r"(addr));
}
static __device__ __forceinline__ float ex2f(float x) {
    float y; asm("ex2.approx.f32 %0, %1;" : "=f"(y) : "f"(x)); return y;
}
static __device__ __forceinline__ float rcpf(float x) {
    float y; asm("rcp.approx.f32 %0, %1;" : "=f"(y) : "f"(x)); return y;
}
static __device__ __forceinline__ float sigf(float x) {
    return rcpf(1.0f + ex2f(-1.4426950408889634f * x));
}
static __device__ __forceinline__ float tanhf_(float x) {
    return fmaf(2.0f, rcpf(1.0f + ex2f(-2.8853900817779268f * x)), -1.0f);
}
static __device__ __forceinline__ uint32_t packbf(float a, float b) {
    __nv_bfloat16 ha = __float2bfloat16_rn(a), hb = __float2bfloat16_rn(b);
    uint32_t r;
    asm("mov.b32 %0, {%1, %2};" : "=r"(r)
        : "h"(__bfloat16_as_ushort(ha)), "h"(__bfloat16_as_ushort(hb)));
    return r;
}

__global__ void __launch_bounds__(NTHREADS, 1)
lstm_hmma_kernel(const float* __restrict__ x,
                 const float* __restrict__ w_ih,
                 const float* __restrict__ w_hh,
                 const float* __restrict__ b_ih,
                 const float* __restrict__ b_hh,
                 const float* __restrict__ w_out,
                 const float* __restrict__ b_out,
                 float* __restrict__ out)
{
    extern __shared__ __align__(16) unsigned char smem[];
    const uint32_t sb = smem_u32(smem);
    float* Xsf = (float*)(smem + OFF_X);

    const int tid  = threadIdx.x;
    const int lane = tid & 31;
    const int warp = tid >> 5;
    const int w7   = warp & 7;      // j block
    const int mgw  = warp >> 3;     // row half (0: rows 0-15, 1: rows 16-31)
    const int gid  = lane >> 2;
    const int tig  = lane & 3;
    const int B0   = blockIdx.x * 32;

    // ---- persistent W B-fragments: n = g*64 + 8*w7 + gid ----
    uint32_t Whi[4][4][2], Wlo[4][4][2];
#pragma unroll
    for (int g = 0; g < 4; ++g)
#pragma unroll
        for (int kc = 0; kc < 4; ++kc) {
            int n = g * 64 + 8 * w7 + gid;
            const float* wr = w_hh + n * HID + 16 * kc;
            float2 fa = *(const float2*)(wr + 2 * tig);
            float2 fb = *(const float2*)(wr + 2 * tig + 8);
            __nv_bfloat16 hax = __float2bfloat16_rn(fa.x);
            __nv_bfloat16 hay = __float2bfloat16_rn(fa.y);
            __nv_bfloat16 hbx = __float2bfloat16_rn(fb.x);
            __nv_bfloat16 hby = __float2bfloat16_rn(fb.y);
            Whi[g][kc][0] = packbf(fa.x, fa.y);
            Whi[g][kc][1] = packbf(fb.x, fb.y);
            Wlo[g][kc][0] = packbf(fa.x - __bfloat162float(hax),
                                   fa.y - __bfloat162float(hay));
            Wlo[g][kc][1] = packbf(fb.x - __bfloat162float(hbx),
                                   fb.y - __bfloat162float(hby));
        }

    float wihr[4][2], biasr[4][2];
#pragma unroll
    for (int g = 0; g < 4; ++g)
#pragma unroll
        for (int jj = 0; jj < 2; ++jj) {
            int n = g * 64 + 8 * w7 + 2 * tig + jj;
            wihr[g][jj]  = w_ih[n];
            biasr[g][jj] = b_ih[n] + b_hh[n];
        }

    // ---- stage x[32, 512] into padded smem; zero h buffers ----
    for (int i = tid; i < 32 * (T_LEN / 4); i += NTHREADS) {
        int b = i / (T_LEN / 4), t4 = i % (T_LEN / 4);
        float4 v = ((const float4*)x)[(size_t)(B0 + b) * (T_LEN / 4) + t4];
        *(float4*)(Xsf + b * XS + 4 * t4) = v;
    }
    for (int i = tid; i < 4 * HSZ / 4; i += NTHREADS)
        ((uint32_t*)(smem + OFF_H))[i] = 0u;
    __syncthreads();

    const uint32_t aoff =
        ((lane & 7) + 8 * ((lane >> 3) & 1)) * HS + 16 * ((lane >> 4) & 1)
        + mgw * 16 * HS;

    float c[4];
#pragma unroll
    for (int s = 0; s < 4; ++s) c[s] = 0.0f;

#pragma unroll 1
    for (int t0 = 0; t0 < T_LEN; t0 += 2) {
#pragma unroll
        for (int tt = 0; tt < 2; ++tt) {
            const int t  = t0 + tt;
            const uint32_t Hr = sb + OFF_H + (tt * 2) * HSZ;        // read
            unsigned char* Hwp = smem + OFF_H + ((tt ^ 1) * 2) * HSZ; // write

            uint32_t A[4][4];
            float D[4][4];
#pragma unroll
            for (int g = 0; g < 4; ++g)
#pragma unroll
                for (int e = 0; e < 4; ++e) D[g][e] = 0.0f;

            // A = h_hi: terms HH, HL
#pragma unroll
            for (int kc = 0; kc < 4; ++kc)
                ldsm4(A[kc], Hr + kc * 32 + aoff);
#pragma unroll
            for (int kc = 0; kc < 4; ++kc)
#pragma unroll
                for (int g = 0; g < 4; ++g)
                    mma16816(D[g], A[kc], Whi[g][kc]);
#pragma unroll
            for (int kc = 0; kc < 4; ++kc)
#pragma unroll
                for (int g = 0; g < 4; ++g)
                    mma16816(D[g], A[kc], Wlo[g][kc]);
            // A = h_lo: term LH
#pragma unroll
            for (int kc = 0; kc < 4; ++kc)
                ldsm4(A[kc], Hr + HSZ + kc * 32 + aoff);
#pragma unroll
            for (int kc = 0; kc < 4; ++kc)
#pragma unroll
                for (int g = 0; g < 4; ++g)
                    mma16816(D[g], A[kc], Whi[g][kc]);

            // epilogue: rows 16*mgw + 8*rh + gid; j = 8*w7 + 2*tig + jj
#pragma unroll
            for (int rh = 0; rh < 2; ++rh) {
                const float xp = Xsf[(16 * mgw + 8 * rh + gid) * XS + t];
                float h2[2];
#pragma unroll
                for (int jj = 0; jj < 2; ++jj) {
                    const int di = rh * 2 + jj;
                    const int s  = rh * 2 + jj;
                    float Pi = D[0][di] + fmaf(xp, wihr[0][jj], biasr[0][jj]);
                    float Pf = D[1][di] + fmaf(xp, wihr[1][jj], biasr[1][jj]);
                    float Pg = D[2][di] + fmaf(xp, wihr[2][jj], biasr[2][jj]);
                    float Po = D[3][di] + fmaf(xp, wihr[3][jj], biasr[3][jj]);
                    float ii = sigf(Pi);
                    float ff = sigf(Pf);
                    float gg = tanhf_(Pg);
                    float oo = sigf(Po);
                    float cs = fmaf(ff, c[s], ii * gg);
                    c[s] = cs;
                    h2[jj] = oo * tanhf_(cs);
                }
                __nv_bfloat16 h0 = __float2bfloat16_rn(h2[0]);
                __nv_bfloat16 h1 = __float2bfloat16_rn(h2[1]);
                uint32_t phi = packbf(h2[0], h2[1]);
                uint32_t plo = packbf(h2[0] - __bfloat162float(h0),
                                      h2[1] - __bfloat162float(h1));
                unsigned char* wp = Hwp + (16 * mgw + 8 * rh + gid) * HS
                                        + 16 * w7 + 4 * tig;
                *(uint32_t*)wp = phi;
                *(uint32_t*)(wp + HSZ) = plo;
            }
            __syncthreads();
        }
    }

    // final h in buffer 0 (t=511: tt=1 wrote buf 0)
    if (tid < 32) {
        const int b = tid;
        float acc = b_out[0];
        const unsigned char* hr = smem + OFF_H + b * HS;
#pragma unroll 8
        for (int k = 0; k < HID; ++k) {
            float hi = __bfloat162float(*(const __nv_bfloat16*)(hr + 2 * k));
            float lo = __bfloat162float(*(const __nv_bfloat16*)(hr + HSZ + 2 * k));
            acc = fmaf(hi + lo, w_out[k], acc);
        }
        out[B0 + b] = acc;
    }
}

extern "C" void kernel_launch(void* const* d_in, const int* in_sizes, int n_in,
                              void* d_out, int out_size) {
    const float* x     = (const float*)d_in[0];
    const float* w_ih  = (const float*)d_in[1];
    const float* w_hh  = (const float*)d_in[2];
    const float* b_ih  = (const float*)d_in[3];
    const float* b_hh  = (const float*)d_in[4];
    const float* w_out = (const float*)d_in[5];
    const float* b_out = (const float*)d_in[6];
    float* out = (float*)d_out;

    cudaFuncSetAttribute(lstm_hmma_kernel,
                         cudaFuncAttributeMaxDynamicSharedMemorySize, SMEM_BYTES);
    lstm_hmma_kernel<<<4096 / 32, NTHREADS, SMEM_BYTES>>>(
        x, w_ih, w_hh, b_ih, b_hh, w_out, b_out, out);
}